// round 13
// baseline (speedup 1.0000x reference)
#include <cuda_runtime.h>
#include <cuda_fp16.h>
#include <cstdint>

#define NN 50000
#define NE 800000
#define NH 25000

// ---------------- device scratch (no allocs allowed) ----------------
__device__ __align__(16) __half g_h16A[NN * 128];
__device__ __align__(16) __half g_h16B[NN * 128];
__device__ __align__(16) __half g_x16[NN * 128];
__device__ __align__(16) __half g_whi[5 * 128 * 128];
__device__ __align__(16) __half g_wlo[5 * 128 * 128];
__device__ int   g_deg[NN];
__device__ float g_invdeg[NN];
__device__ int   g_rowptr[NN + 1];
__device__ int   g_epos[NE];
__device__ int   g_esrc[NE];

// ---------------- helpers ----------------
__device__ __forceinline__ uint32_t smem_u32(const void* p) {
    uint32_t a;
    asm("{ .reg .u64 t; cvta.to.shared.u64 t, %1; cvt.u32.u64 %0, t; }" : "=r"(a) : "l"(p));
    return a;
}

__device__ __forceinline__ void ldsm4(uint32_t* r, uint32_t addr) {
    asm volatile("ldmatrix.sync.aligned.m8n8.x4.shared.b16 {%0,%1,%2,%3}, [%4];"
                 : "=r"(r[0]), "=r"(r[1]), "=r"(r[2]), "=r"(r[3]) : "r"(addr));
}

__device__ __forceinline__ void mma_fp16(float* c, const uint32_t* a, const uint32_t* b) {
    asm volatile(
        "mma.sync.aligned.m16n8k16.row.col.f32.f16.f16.f32 "
        "{%0,%1,%2,%3}, {%4,%5,%6,%7}, {%8,%9}, {%0,%1,%2,%3};"
        : "+f"(c[0]), "+f"(c[1]), "+f"(c[2]), "+f"(c[3])
        : "r"(a[0]), "r"(a[1]), "r"(a[2]), "r"(a[3]), "r"(b[0]), "r"(b[1]));
}

__device__ __forceinline__ void split_fp16(float v, __half& hi, __half& lo) {
    hi = __float2half_rn(v);
    lo = __float2half_rn(v - __half2float(hi));
}
__device__ __forceinline__ uint32_t pack2h(__half a, __half b) {
    __half2 t = __halves2half2(a, b);
    return *reinterpret_cast<uint32_t*>(&t);
}

// ---------------- CSR build ----------------
__global__ void zero_deg_kernel() {
    int v = blockIdx.x * blockDim.x + threadIdx.x;
    if (v < NN) g_deg[v] = 0;
}

__global__ void hist_kernel(const int* __restrict__ dst) {
    int i = blockIdx.x * blockDim.x + threadIdx.x;
    if (i * 4 + 3 < NE) {
        int4 d = ((const int4*)dst)[i];
        int4 p;
        p.x = atomicAdd(&g_deg[d.x], 1);
        p.y = atomicAdd(&g_deg[d.y], 1);
        p.z = atomicAdd(&g_deg[d.z], 1);
        p.w = atomicAdd(&g_deg[d.w], 1);
        ((int4*)g_epos)[i] = p;
    } else {
        for (int e = i * 4; e < NE; ++e) g_epos[e] = atomicAdd(&g_deg[dst[e]], 1);
    }
}

__global__ void scan_kernel() {
    __shared__ int partial[1024];
    int t = threadIdx.x;
    const int C = (NN + 1023) / 1024;
    int beg = t * C;
    int end = min(beg + C, NN);
    int s = 0;
    for (int v = beg; v < end; ++v) s += g_deg[v];
    partial[t] = s;
    __syncthreads();
    for (int off = 1; off < 1024; off <<= 1) {
        int val = (t >= off) ? partial[t - off] : 0;
        __syncthreads();
        partial[t] += val;
        __syncthreads();
    }
    int run = (t == 0) ? 0 : partial[t - 1];
    for (int v = beg; v < end; ++v) {
        int d = g_deg[v];
        g_rowptr[v] = run;
        g_invdeg[v] = 1.0f / (float)(d > 0 ? d : 1);
        run += d;
    }
    if (t == 1023) g_rowptr[NN] = run;
}

__global__ void fill_kernel(const int* __restrict__ src, const int* __restrict__ dst) {
    int i = blockIdx.x * blockDim.x + threadIdx.x;
    if (i * 4 + 3 < NE) {
        int4 s = ((const int4*)src)[i];
        int4 d = ((const int4*)dst)[i];
        int4 p = ((const int4*)g_epos)[i];
        g_esrc[g_rowptr[d.x] + p.x] = s.x;
        g_esrc[g_rowptr[d.y] + p.y] = s.y;
        g_esrc[g_rowptr[d.z] + p.z] = s.z;
        g_esrc[g_rowptr[d.w] + p.w] = s.w;
    } else {
        for (int e = i * 4; e < NE; ++e)
            g_esrc[g_rowptr[dst[e]] + g_epos[e]] = src[e];
    }
}

// ---------------- merged fp32 -> fp16 hi/lo split for all 5 weight mats ----------------
__global__ void convert_weights_kernel(const float* __restrict__ fcW,
                                       const float* __restrict__ W,
                                       const float* __restrict__ WL,
                                       __half* __restrict__ ohi,
                                       __half* __restrict__ olo) {
    int i = blockIdx.x * blockDim.x + threadIdx.x;
    if (i >= 18432) return;
    const float* srcp;
    if (i < 4096) srcp = fcW + 4 * (size_t)i;
    else if (i < 16384) srcp = W + 4 * (size_t)(i - 4096);
    else srcp = WL + 4 * (size_t)(i - 16384);
    float4 v = *(const float4*)srcp;
    __half h0, l0, h1, l1, h2, l2, h3, l3;
    split_fp16(v.x, h0, l0);
    split_fp16(v.y, h1, l1);
    split_fp16(v.z, h2, l2);
    split_fp16(v.w, h3, l3);
    uint2 uh, ul;
    uh.x = pack2h(h0, h1); uh.y = pack2h(h2, h3);
    ul.x = pack2h(l0, l1); ul.y = pack2h(l2, l3);
    ((uint2*)ohi)[i] = uh;
    ((uint2*)olo)[i] = ul;
}

// ---------------- aggregation: warp-per-node over [vbeg, vend) ----------------
__global__ void aggregate_kernel(const __half* __restrict__ h16,
                                 __half* __restrict__ x16,
                                 const float* __restrict__ eps, int li,
                                 int vbeg, int vend) {
    int v = vbeg + ((blockIdx.x * blockDim.x + threadIdx.x) >> 5);
    if (v >= vend) return;
    int lane = threadIdx.x & 31;
    int beg = g_rowptr[v], end = g_rowptr[v + 1];
    float4 acc = make_float4(0.f, 0.f, 0.f, 0.f);
    int e = beg;
    int col = lane * 4;
#define GATH(uv)                                                        \
    {                                                                   \
        __half2 p0 = *reinterpret_cast<const __half2*>(&(uv).x);        \
        __half2 p1 = *reinterpret_cast<const __half2*>(&(uv).y);        \
        float2 f0 = __half22float2(p0);                                 \
        float2 f1 = __half22float2(p1);                                 \
        acc.x += f0.x; acc.y += f0.y; acc.z += f1.x; acc.w += f1.y;     \
    }
    for (; e + 8 <= end; e += 8) {
        uint2 a0 = *(const uint2*)(h16 + (size_t)g_esrc[e + 0] * 128 + col);
        uint2 a1 = *(const uint2*)(h16 + (size_t)g_esrc[e + 1] * 128 + col);
        uint2 a2 = *(const uint2*)(h16 + (size_t)g_esrc[e + 2] * 128 + col);
        uint2 a3 = *(const uint2*)(h16 + (size_t)g_esrc[e + 3] * 128 + col);
        uint2 a4 = *(const uint2*)(h16 + (size_t)g_esrc[e + 4] * 128 + col);
        uint2 a5 = *(const uint2*)(h16 + (size_t)g_esrc[e + 5] * 128 + col);
        uint2 a6 = *(const uint2*)(h16 + (size_t)g_esrc[e + 6] * 128 + col);
        uint2 a7 = *(const uint2*)(h16 + (size_t)g_esrc[e + 7] * 128 + col);
        GATH(a0); GATH(a1); GATH(a2); GATH(a3);
        GATH(a4); GATH(a5); GATH(a6); GATH(a7);
    }
    for (; e + 4 <= end; e += 4) {
        uint2 a0 = *(const uint2*)(h16 + (size_t)g_esrc[e + 0] * 128 + col);
        uint2 a1 = *(const uint2*)(h16 + (size_t)g_esrc[e + 1] * 128 + col);
        uint2 a2 = *(const uint2*)(h16 + (size_t)g_esrc[e + 2] * 128 + col);
        uint2 a3 = *(const uint2*)(h16 + (size_t)g_esrc[e + 3] * 128 + col);
        GATH(a0); GATH(a1); GATH(a2); GATH(a3);
    }
    for (; e < end; ++e) {
        uint2 a = *(const uint2*)(h16 + (size_t)g_esrc[e] * 128 + col);
        GATH(a);
    }
#undef GATH
    float inv = g_invdeg[v];
    float sc = 1.0f + eps[li];
    uint2 sh = *(const uint2*)(h16 + (size_t)v * 128 + col);
    float2 s0 = __half22float2(*reinterpret_cast<const __half2*>(&sh.x));
    float2 s1 = __half22float2(*reinterpret_cast<const __half2*>(&sh.y));
    uint2 o;
    o.x = pack2h(__float2half_rn(sc * s0.x + acc.x * inv),
                 __float2half_rn(sc * s0.y + acc.y * inv));
    o.y = pack2h(__float2half_rn(sc * s1.x + acc.z * inv),
                 __float2half_rn(sc * s1.y + acc.w * inv));
    *(uint2*)&x16[(size_t)v * 128 + col] = o;
}

// ---------------- tensor-core GEMM: BM=64, 2-product fp16, rows [mbeg, mend) ----------------
template <int N, bool RELU, bool ASPLIT, bool F32OUT>
__global__ void __launch_bounds__(256, 3) gemm_mma(
    const float* __restrict__ A32, const __half* __restrict__ A16,
    const __half* __restrict__ Bhi, const __half* __restrict__ Blo,
    const float* __restrict__ bias, float* __restrict__ out, __half* __restrict__ out16,
    int mbeg, int mend) {
    constexpr int BM = 64;
    constexpr int LD = 72;
    constexpr int NWN = N / 32;
    constexpr int NWM = 8 / NWN;
    constexpr int MW = BM / NWM;
    constexpr int MT = MW / 16;

    extern __shared__ __half sm[];
    __half* sA = sm;
    __half* sBhi = sA + BM * LD;
    __half* sBlo = sBhi + N * LD;
    __shared__ float s_bias[128];

    int tid = threadIdx.x;
    int lane = tid & 31;
    int wid = tid >> 5;
    int wm = wid / NWN;
    int wn = wid % NWN;
    int m0 = mbeg + blockIdx.x * BM;
    if (tid < N) s_bias[tid] = bias[tid];

    float acc[MT][4][4];
#pragma unroll
    for (int mt = 0; mt < MT; ++mt)
#pragma unroll
        for (int nt = 0; nt < 4; ++nt)
#pragma unroll
            for (int q = 0; q < 4; ++q) acc[mt][nt][q] = 0.f;

    const int ar = lane & 15;
    const int ak = (lane >> 4) << 3;
    const int br = (lane & 7) + ((lane >> 4) << 3);
    const int bk = ((lane >> 3) & 1) << 3;

#pragma unroll
    for (int kc = 0; kc < 2; ++kc) {
        int kg = kc * 64;
        for (int i = tid; i < N * 8; i += 256) {
            int row = i >> 3;
            int c8 = (i & 7) << 3;
            *(uint4*)&sBhi[row * LD + c8] = *(const uint4*)(Bhi + (size_t)row * 128 + kg + c8);
            *(uint4*)&sBlo[row * LD + c8] = *(const uint4*)(Blo + (size_t)row * 128 + kg + c8);
        }
        if (ASPLIT) {
            for (int i = tid; i < BM * 8; i += 256) {
                int row = i >> 3;
                int c8 = (i & 7) << 3;
                int gm = m0 + row;
                float4 v0 = make_float4(0.f, 0.f, 0.f, 0.f);
                float4 v1 = make_float4(0.f, 0.f, 0.f, 0.f);
                if (gm < mend) {
                    v0 = *(const float4*)(A32 + (size_t)gm * 128 + kg + c8);
                    v1 = *(const float4*)(A32 + (size_t)gm * 128 + kg + c8 + 4);
                }
                uint4 u;
                u.x = pack2h(__float2half_rn(v0.x), __float2half_rn(v0.y));
                u.y = pack2h(__float2half_rn(v0.z), __float2half_rn(v0.w));
                u.z = pack2h(__float2half_rn(v1.x), __float2half_rn(v1.y));
                u.w = pack2h(__float2half_rn(v1.z), __float2half_rn(v1.w));
                *(uint4*)&sA[row * LD + c8] = u;
            }
        } else {
            for (int i = tid; i < BM * 8; i += 256) {
                int row = i >> 3;
                int c8 = (i & 7) << 3;
                int gm = m0 + row;
                uint4 u = make_uint4(0, 0, 0, 0);
                if (gm < mend) u = *(const uint4*)(A16 + (size_t)gm * 128 + kg + c8);
                *(uint4*)&sA[row * LD + c8] = u;
            }
        }
        __syncthreads();

#pragma unroll
        for (int ks = 0; ks < 4; ++ks) {
            int k0 = ks << 4;
            uint32_t a[MT][4];
#pragma unroll
            for (int mt = 0; mt < MT; ++mt) {
                int row = wm * MW + mt * 16 + ar;
                ldsm4(a[mt], smem_u32(&sA[row * LD + k0 + ak]));
            }
            uint32_t bh[4][2], bl[4][2];
#pragma unroll
            for (int p = 0; p < 2; ++p) {
                int nrow = wn * 32 + p * 16 + br;
                uint32_t r[4];
                ldsm4(r, smem_u32(&sBhi[nrow * LD + k0 + bk]));
                bh[2 * p][0] = r[0]; bh[2 * p][1] = r[1];
                bh[2 * p + 1][0] = r[2]; bh[2 * p + 1][1] = r[3];
                ldsm4(r, smem_u32(&sBlo[nrow * LD + k0 + bk]));
                bl[2 * p][0] = r[0]; bl[2 * p][1] = r[1];
                bl[2 * p + 1][0] = r[2]; bl[2 * p + 1][1] = r[3];
            }
#pragma unroll
            for (int mt = 0; mt < MT; ++mt)
#pragma unroll
                for (int nt = 0; nt < 4; ++nt) {
                    mma_fp16(acc[mt][nt], a[mt], bh[nt]);
                    mma_fp16(acc[mt][nt], a[mt], bl[nt]);
                }
        }
        __syncthreads();
    }

    int r = lane >> 2;
    int c2 = (lane & 3) << 1;
#pragma unroll
    for (int mt = 0; mt < MT; ++mt) {
        int gm = m0 + wm * MW + mt * 16 + r;
#pragma unroll
        for (int nt = 0; nt < 4; ++nt) {
            int col = wn * 32 + nt * 8 + c2;
            float b0 = s_bias[col], b1 = s_bias[col + 1];
            if (gm < mend) {
                float2 v = make_float2(acc[mt][nt][0] + b0, acc[mt][nt][1] + b1);
                if (RELU) { v.x = fmaxf(v.x, 0.f); v.y = fmaxf(v.y, 0.f); }
                if (F32OUT)
                    *(float2*)(out + (size_t)gm * N + col) = v;
                else
                    *(uint32_t*)(out16 + (size_t)gm * N + col) =
                        pack2h(__float2half_rn(v.x), __float2half_rn(v.y));
            }
            if (gm + 8 < mend) {
                float2 v = make_float2(acc[mt][nt][2] + b0, acc[mt][nt][3] + b1);
                if (RELU) { v.x = fmaxf(v.x, 0.f); v.y = fmaxf(v.y, 0.f); }
                if (F32OUT)
                    *(float2*)(out + (size_t)(gm + 8) * N + col) = v;
                else
                    *(uint32_t*)(out16 + (size_t)(gm + 8) * N + col) =
                        pack2h(__float2half_rn(v.x), __float2half_rn(v.y));
            }
        }
    }
}

// ---------------- launch ----------------
extern "C" void kernel_launch(void* const* d_in, const int* in_sizes, int n_in,
                              void* d_out, int out_size) {
    const float* inputs = (const float*)d_in[0];
    const float* fc_W   = (const float*)d_in[1];
    const float* fc_b   = (const float*)d_in[2];
    const float* W      = (const float*)d_in[3];
    const float* b      = (const float*)d_in[4];
    const float* W_last = (const float*)d_in[5];
    const float* b_last = (const float*)d_in[6];
    const float* eps    = (const float*)d_in[7];
    const int*   src    = (const int*)d_in[8];
    const int*   dst    = (const int*)d_in[9];
    float* out = (float*)d_out;

    __half *h16A, *h16B, *x16, *whi, *wlo;
    cudaGetSymbolAddress((void**)&h16A, g_h16A);
    cudaGetSymbolAddress((void**)&h16B, g_h16B);
    cudaGetSymbolAddress((void**)&x16, g_x16);
    cudaGetSymbolAddress((void**)&whi, g_whi);
    cudaGetSymbolAddress((void**)&wlo, g_wlo);

    const int SMEM128 = (64 * 72 + 2 * 128 * 72) * 2;  // 46080 B
    const int SMEM64  = (64 * 72 + 2 * 64 * 72) * 2;   // 27648 B
    cudaFuncSetAttribute(gemm_mma<128, true, true, false>,  cudaFuncAttributeMaxDynamicSharedMemorySize, SMEM128);
    cudaFuncSetAttribute(gemm_mma<128, true, false, false>, cudaFuncAttributeMaxDynamicSharedMemorySize, SMEM128);
    cudaFuncSetAttribute(gemm_mma<64, false, false, true>,  cudaFuncAttributeMaxDynamicSharedMemorySize, SMEM64);

    // One-time side stream + events (created on the first, non-capture, call).
    static cudaStream_t s_side = nullptr;
    static cudaEvent_t s_fork = nullptr, s_join = nullptr;
    static cudaEvent_t eAgg[4], eB[4];
    if (s_side == nullptr) {
        cudaStreamCreateWithFlags(&s_side, cudaStreamNonBlocking);
        cudaEventCreateWithFlags(&s_fork, cudaEventDisableTiming);
        cudaEventCreateWithFlags(&s_join, cudaEventDisableTiming);
        for (int i = 0; i < 4; ++i) {
            cudaEventCreateWithFlags(&eAgg[i], cudaEventDisableTiming);
            cudaEventCreateWithFlags(&eB[i], cudaEventDisableTiming);
        }
    }

    const int gemm_grid_full = (NN + 63) / 64;   // 782
    const int gemm_grid_half = (NH + 63) / 64;   // 391
    const int agg_grid_half  = (NH + 7) / 8;     // 3125

    // ---- forked phase: CSR build (side) || convert + SLP GEMM (main) ----
    convert_weights_kernel<<<(18432 + 255) / 256, 256>>>(fc_W, W, W_last, whi, wlo);
    cudaEventRecord(s_fork, 0);
    cudaStreamWaitEvent(s_side, s_fork, 0);

    zero_deg_kernel<<<(NN + 255) / 256, 256, 0, s_side>>>();
    hist_kernel<<<(NE / 4 + 255) / 256, 256, 0, s_side>>>(dst);
    gemm_mma<128, true, true, false><<<gemm_grid_full, 256, SMEM128>>>(  // profiled slot
        inputs, nullptr, whi, wlo, fc_b, nullptr, h16A, 0, NN);
    scan_kernel<<<1, 1024, 0, s_side>>>();
    fill_kernel<<<(NE / 4 + 255) / 256, 256, 0, s_side>>>(src, dst);

    cudaEventRecord(s_join, s_side);
    cudaStreamWaitEvent(0, s_join, 0);

    // ---- pipelined layers: aggA -> [gemmA || aggB] -> gemmB, ping-pong h16 ----
    __half* hb[2] = {h16A, h16B};
    for (int i = 0; i < 3; ++i) {
        const __half* hin = hb[i & 1];
        __half* hout = hb[(i + 1) & 1];
        const __half* bwhi = whi + (size_t)(1 + i) * 16384;
        const __half* bwlo = wlo + (size_t)(1 + i) * 16384;
        const float* bb = b + (size_t)i * 128;

        aggregate_kernel<<<agg_grid_half, 256>>>(hin, x16, eps, i, 0, NH);
        cudaEventRecord(eAgg[i], 0);
        gemm_mma<128, true, false, false><<<gemm_grid_half, 256, SMEM128>>>(
            nullptr, x16, bwhi, bwlo, bb, nullptr, hout, 0, NH);

        cudaStreamWaitEvent(s_side, eAgg[i], 0);
        aggregate_kernel<<<agg_grid_half, 256, 0, s_side>>>(hin, x16, eps, i, NH, NN);
        gemm_mma<128, true, false, false><<<gemm_grid_half, 256, SMEM128, s_side>>>(
            nullptr, x16, bwhi, bwlo, bb, nullptr, hout, NH, NN);
        cudaEventRecord(eB[i], s_side);
        cudaStreamWaitEvent(0, eB[i], 0);
    }

    // ---- last layer (no relu), fp32 straight into d_out, same pipeline ----
    {
        const __half* hin = hb[3 & 1];  // h16B after layer 2
        const __half* bwhi = whi + (size_t)4 * 16384;
        const __half* bwlo = wlo + (size_t)4 * 16384;

        aggregate_kernel<<<agg_grid_half, 256>>>(hin, x16, eps, 3, 0, NH);
        cudaEventRecord(eAgg[3], 0);
        gemm_mma<64, false, false, true><<<gemm_grid_half, 256, SMEM64>>>(
            nullptr, x16, bwhi, bwlo, b_last, out, nullptr, 0, NH);

        cudaStreamWaitEvent(s_side, eAgg[3], 0);
        aggregate_kernel<<<agg_grid_half, 256, 0, s_side>>>(hin, x16, eps, 3, NH, NN);
        gemm_mma<64, false, false, true><<<gemm_grid_half, 256, SMEM64, s_side>>>(
            nullptr, x16, bwhi, bwlo, b_last, out, nullptr, NH, NN);
        cudaEventRecord(eB[3], s_side);
        cudaStreamWaitEvent(0, eB[3], 0);
    }

    (void)in_sizes; (void)n_in; (void)out_size;
}

// round 14
// speedup vs baseline: 1.1204x; 1.1204x over previous
#include <cuda_runtime.h>
#include <cuda_fp16.h>
#include <cstdint>

#define NN 50000
#define NE 800000

// ---------------- device scratch (no allocs allowed) ----------------
__device__ __align__(16) __half g_h16[NN * 128];
__device__ __align__(16) __half g_x16[NN * 128];
__device__ __align__(16) __half g_w16[5 * 128 * 128];
__device__ int   g_deg[NN];
__device__ float g_invdeg[NN];
__device__ int   g_rowptr[NN + 1];
__device__ int   g_epos[NE];
__device__ int   g_esrc[NE];

// ---------------- helpers ----------------
__device__ __forceinline__ uint32_t smem_u32(const void* p) {
    uint32_t a;
    asm("{ .reg .u64 t; cvta.to.shared.u64 t, %1; cvt.u32.u64 %0, t; }" : "=r"(a) : "l"(p));
    return a;
}

__device__ __forceinline__ void ldsm4(uint32_t* r, uint32_t addr) {
    asm volatile("ldmatrix.sync.aligned.m8n8.x4.shared.b16 {%0,%1,%2,%3}, [%4];"
                 : "=r"(r[0]), "=r"(r[1]), "=r"(r[2]), "=r"(r[3]) : "r"(addr));
}

__device__ __forceinline__ void mma_fp16(float* c, const uint32_t* a, const uint32_t* b) {
    asm volatile(
        "mma.sync.aligned.m16n8k16.row.col.f32.f16.f16.f32 "
        "{%0,%1,%2,%3}, {%4,%5,%6,%7}, {%8,%9}, {%0,%1,%2,%3};"
        : "+f"(c[0]), "+f"(c[1]), "+f"(c[2]), "+f"(c[3])
        : "r"(a[0]), "r"(a[1]), "r"(a[2]), "r"(a[3]), "r"(b[0]), "r"(b[1]));
}

__device__ __forceinline__ uint32_t pack2h(__half a, __half b) {
    __half2 t = __halves2half2(a, b);
    return *reinterpret_cast<uint32_t*>(&t);
}

// ---------------- CSR build ----------------
__global__ void zero_deg_kernel() {
    int v = blockIdx.x * blockDim.x + threadIdx.x;
    if (v < NN) g_deg[v] = 0;
}

__global__ void hist_kernel(const int* __restrict__ dst) {
    int i = blockIdx.x * blockDim.x + threadIdx.x;
    if (i * 4 + 3 < NE) {
        int4 d = ((const int4*)dst)[i];
        int4 p;
        p.x = atomicAdd(&g_deg[d.x], 1);
        p.y = atomicAdd(&g_deg[d.y], 1);
        p.z = atomicAdd(&g_deg[d.z], 1);
        p.w = atomicAdd(&g_deg[d.w], 1);
        ((int4*)g_epos)[i] = p;
    } else {
        for (int e = i * 4; e < NE; ++e) g_epos[e] = atomicAdd(&g_deg[dst[e]], 1);
    }
}

__global__ void scan_kernel() {
    __shared__ int partial[1024];
    int t = threadIdx.x;
    const int C = (NN + 1023) / 1024;
    int beg = t * C;
    int end = min(beg + C, NN);
    int s = 0;
    for (int v = beg; v < end; ++v) s += g_deg[v];
    partial[t] = s;
    __syncthreads();
    for (int off = 1; off < 1024; off <<= 1) {
        int val = (t >= off) ? partial[t - off] : 0;
        __syncthreads();
        partial[t] += val;
        __syncthreads();
    }
    int run = (t == 0) ? 0 : partial[t - 1];
    for (int v = beg; v < end; ++v) {
        int d = g_deg[v];
        g_rowptr[v] = run;
        g_invdeg[v] = 1.0f / (float)(d > 0 ? d : 1);
        run += d;
    }
    if (t == 1023) g_rowptr[NN] = run;
}

__global__ void fill_kernel(const int* __restrict__ src, const int* __restrict__ dst) {
    int i = blockIdx.x * blockDim.x + threadIdx.x;
    if (i * 4 + 3 < NE) {
        int4 s = ((const int4*)src)[i];
        int4 d = ((const int4*)dst)[i];
        int4 p = ((const int4*)g_epos)[i];
        g_esrc[g_rowptr[d.x] + p.x] = s.x;
        g_esrc[g_rowptr[d.y] + p.y] = s.y;
        g_esrc[g_rowptr[d.z] + p.z] = s.z;
        g_esrc[g_rowptr[d.w] + p.w] = s.w;
    } else {
        for (int e = i * 4; e < NE; ++e)
            g_esrc[g_rowptr[dst[e]] + g_epos[e]] = src[e];
    }
}

// ---------------- merged fp32 -> fp16 convert for all 5 weight mats ----------------
__global__ void convert_weights_kernel(const float* __restrict__ fcW,
                                       const float* __restrict__ W,
                                       const float* __restrict__ WL,
                                       __half* __restrict__ o16) {
    int i = blockIdx.x * blockDim.x + threadIdx.x;
    if (i >= 18432) return;
    const float* srcp;
    if (i < 4096) srcp = fcW + 4 * (size_t)i;
    else if (i < 16384) srcp = W + 4 * (size_t)(i - 4096);
    else srcp = WL + 4 * (size_t)(i - 16384);
    float4 v = *(const float4*)srcp;
    uint2 u;
    u.x = pack2h(__float2half_rn(v.x), __float2half_rn(v.y));
    u.y = pack2h(__float2half_rn(v.z), __float2half_rn(v.w));
    ((uint2*)o16)[i] = u;
}

// ---------------- aggregation: warp-per-node, all-fp16 gather + self ----------------
__global__ void aggregate_kernel(const __half* __restrict__ h16,
                                 __half* __restrict__ x16,
                                 const float* __restrict__ eps, int li) {
    int warp = (blockIdx.x * blockDim.x + threadIdx.x) >> 5;
    if (warp >= NN) return;
    int lane = threadIdx.x & 31;
    int v = warp;
    int beg = g_rowptr[v], end = g_rowptr[v + 1];
    float4 acc = make_float4(0.f, 0.f, 0.f, 0.f);
    int e = beg;
    int col = lane * 4;
#define GATH(uv)                                                        \
    {                                                                   \
        __half2 p0 = *reinterpret_cast<const __half2*>(&(uv).x);        \
        __half2 p1 = *reinterpret_cast<const __half2*>(&(uv).y);        \
        float2 f0 = __half22float2(p0);                                 \
        float2 f1 = __half22float2(p1);                                 \
        acc.x += f0.x; acc.y += f0.y; acc.z += f1.x; acc.w += f1.y;     \
    }
    for (; e + 8 <= end; e += 8) {
        uint2 a0 = *(const uint2*)(h16 + (size_t)g_esrc[e + 0] * 128 + col);
        uint2 a1 = *(const uint2*)(h16 + (size_t)g_esrc[e + 1] * 128 + col);
        uint2 a2 = *(const uint2*)(h16 + (size_t)g_esrc[e + 2] * 128 + col);
        uint2 a3 = *(const uint2*)(h16 + (size_t)g_esrc[e + 3] * 128 + col);
        uint2 a4 = *(const uint2*)(h16 + (size_t)g_esrc[e + 4] * 128 + col);
        uint2 a5 = *(const uint2*)(h16 + (size_t)g_esrc[e + 5] * 128 + col);
        uint2 a6 = *(const uint2*)(h16 + (size_t)g_esrc[e + 6] * 128 + col);
        uint2 a7 = *(const uint2*)(h16 + (size_t)g_esrc[e + 7] * 128 + col);
        GATH(a0); GATH(a1); GATH(a2); GATH(a3);
        GATH(a4); GATH(a5); GATH(a6); GATH(a7);
    }
    for (; e + 4 <= end; e += 4) {
        uint2 a0 = *(const uint2*)(h16 + (size_t)g_esrc[e + 0] * 128 + col);
        uint2 a1 = *(const uint2*)(h16 + (size_t)g_esrc[e + 1] * 128 + col);
        uint2 a2 = *(const uint2*)(h16 + (size_t)g_esrc[e + 2] * 128 + col);
        uint2 a3 = *(const uint2*)(h16 + (size_t)g_esrc[e + 3] * 128 + col);
        GATH(a0); GATH(a1); GATH(a2); GATH(a3);
    }
    for (; e < end; ++e) {
        uint2 a = *(const uint2*)(h16 + (size_t)g_esrc[e] * 128 + col);
        GATH(a);
    }
#undef GATH
    float inv = g_invdeg[v];
    float sc = 1.0f + eps[li];
    uint2 sh = *(const uint2*)(h16 + (size_t)v * 128 + col);
    float2 s0 = __half22float2(*reinterpret_cast<const __half2*>(&sh.x));
    float2 s1 = __half22float2(*reinterpret_cast<const __half2*>(&sh.y));
    uint2 o;
    o.x = pack2h(__float2half_rn(sc * s0.x + acc.x * inv),
                 __float2half_rn(sc * s0.y + acc.y * inv));
    o.y = pack2h(__float2half_rn(sc * s1.x + acc.z * inv),
                 __float2half_rn(sc * s1.y + acc.w * inv));
    *(uint2*)&x16[(size_t)v * 128 + col] = o;
}

// ---------------- tensor-core GEMM: BM=64, single fp16 product, 4 CTAs/SM ----------------
// out[M,N] = act(A @ W16^T + bias);  K chunked 2x64.
template <int N, bool RELU, bool ASPLIT, bool F32OUT>
__global__ void __launch_bounds__(256, 4) gemm_mma(
    const float* __restrict__ A32, const __half* __restrict__ A16,
    const __half* __restrict__ B16,
    const float* __restrict__ bias, float* __restrict__ out, __half* __restrict__ out16,
    int M) {
    constexpr int BM = 64;
    constexpr int LD = 72;
    constexpr int NWN = N / 32;
    constexpr int NWM = 8 / NWN;
    constexpr int MW = BM / NWM;
    constexpr int MT = MW / 16;

    extern __shared__ __half sm[];
    __half* sA = sm;                 // BM x LD
    __half* sB = sA + BM * LD;       // N x LD
    __shared__ float s_bias[128];

    int tid = threadIdx.x;
    int lane = tid & 31;
    int wid = tid >> 5;
    int wm = wid / NWN;
    int wn = wid % NWN;
    int m0 = blockIdx.x * BM;
    if (tid < N) s_bias[tid] = bias[tid];

    float acc[MT][4][4];
#pragma unroll
    for (int mt = 0; mt < MT; ++mt)
#pragma unroll
        for (int nt = 0; nt < 4; ++nt)
#pragma unroll
            for (int q = 0; q < 4; ++q) acc[mt][nt][q] = 0.f;

    const int ar = lane & 15;
    const int ak = (lane >> 4) << 3;
    const int br = (lane & 7) + ((lane >> 4) << 3);
    const int bk = ((lane >> 3) & 1) << 3;

#pragma unroll
    for (int kc = 0; kc < 2; ++kc) {
        int kg = kc * 64;
        for (int i = tid; i < N * 8; i += 256) {
            int row = i >> 3;
            int c8 = (i & 7) << 3;
            *(uint4*)&sB[row * LD + c8] = *(const uint4*)(B16 + (size_t)row * 128 + kg + c8);
        }
        if (ASPLIT) {
            for (int i = tid; i < BM * 8; i += 256) {
                int row = i >> 3;
                int c8 = (i & 7) << 3;
                int gm = m0 + row;
                float4 v0 = make_float4(0.f, 0.f, 0.f, 0.f);
                float4 v1 = make_float4(0.f, 0.f, 0.f, 0.f);
                if (gm < M) {
                    v0 = *(const float4*)(A32 + (size_t)gm * 128 + kg + c8);
                    v1 = *(const float4*)(A32 + (size_t)gm * 128 + kg + c8 + 4);
                }
                uint4 u;
                u.x = pack2h(__float2half_rn(v0.x), __float2half_rn(v0.y));
                u.y = pack2h(__float2half_rn(v0.z), __float2half_rn(v0.w));
                u.z = pack2h(__float2half_rn(v1.x), __float2half_rn(v1.y));
                u.w = pack2h(__float2half_rn(v1.z), __float2half_rn(v1.w));
                *(uint4*)&sA[row * LD + c8] = u;
            }
        } else {
            for (int i = tid; i < BM * 8; i += 256) {
                int row = i >> 3;
                int c8 = (i & 7) << 3;
                int gm = m0 + row;
                uint4 u = make_uint4(0, 0, 0, 0);
                if (gm < M) u = *(const uint4*)(A16 + (size_t)gm * 128 + kg + c8);
                *(uint4*)&sA[row * LD + c8] = u;
            }
        }
        __syncthreads();

#pragma unroll
        for (int ks = 0; ks < 4; ++ks) {
            int k0 = ks << 4;
            uint32_t a[MT][4];
#pragma unroll
            for (int mt = 0; mt < MT; ++mt) {
                int row = wm * MW + mt * 16 + ar;
                ldsm4(a[mt], smem_u32(&sA[row * LD + k0 + ak]));
            }
            uint32_t bb[4][2];
#pragma unroll
            for (int p = 0; p < 2; ++p) {
                int nrow = wn * 32 + p * 16 + br;
                uint32_t r[4];
                ldsm4(r, smem_u32(&sB[nrow * LD + k0 + bk]));
                bb[2 * p][0] = r[0]; bb[2 * p][1] = r[1];
                bb[2 * p + 1][0] = r[2]; bb[2 * p + 1][1] = r[3];
            }
#pragma unroll
            for (int mt = 0; mt < MT; ++mt)
#pragma unroll
                for (int nt = 0; nt < 4; ++nt)
                    mma_fp16(acc[mt][nt], a[mt], bb[nt]);
        }
        __syncthreads();
    }

    int r = lane >> 2;
    int c2 = (lane & 3) << 1;
#pragma unroll
    for (int mt = 0; mt < MT; ++mt) {
        int gm = m0 + wm * MW + mt * 16 + r;
#pragma unroll
        for (int nt = 0; nt < 4; ++nt) {
            int col = wn * 32 + nt * 8 + c2;
            float b0 = s_bias[col], b1 = s_bias[col + 1];
            if (gm < M) {
                float2 v = make_float2(acc[mt][nt][0] + b0, acc[mt][nt][1] + b1);
                if (RELU) { v.x = fmaxf(v.x, 0.f); v.y = fmaxf(v.y, 0.f); }
                if (F32OUT)
                    *(float2*)(out + (size_t)gm * N + col) = v;
                else
                    *(uint32_t*)(out16 + (size_t)gm * N + col) =
                        pack2h(__float2half_rn(v.x), __float2half_rn(v.y));
            }
            if (gm + 8 < M) {
                float2 v = make_float2(acc[mt][nt][2] + b0, acc[mt][nt][3] + b1);
                if (RELU) { v.x = fmaxf(v.x, 0.f); v.y = fmaxf(v.y, 0.f); }
                if (F32OUT)
                    *(float2*)(out + (size_t)(gm + 8) * N + col) = v;
                else
                    *(uint32_t*)(out16 + (size_t)(gm + 8) * N + col) =
                        pack2h(__float2half_rn(v.x), __float2half_rn(v.y));
            }
        }
    }
}

// ---------------- launch ----------------
extern "C" void kernel_launch(void* const* d_in, const int* in_sizes, int n_in,
                              void* d_out, int out_size) {
    const float* inputs = (const float*)d_in[0];
    const float* fc_W   = (const float*)d_in[1];
    const float* fc_b   = (const float*)d_in[2];
    const float* W      = (const float*)d_in[3];
    const float* b      = (const float*)d_in[4];
    const float* W_last = (const float*)d_in[5];
    const float* b_last = (const float*)d_in[6];
    const float* eps    = (const float*)d_in[7];
    const int*   src    = (const int*)d_in[8];
    const int*   dst    = (const int*)d_in[9];
    float* out = (float*)d_out;

    __half *h16, *x16, *w16;
    cudaGetSymbolAddress((void**)&h16, g_h16);
    cudaGetSymbolAddress((void**)&x16, g_x16);
    cudaGetSymbolAddress((void**)&w16, g_w16);

    const int SMEM128 = (64 * 72 + 128 * 72) * 2;  // 27648 B
    const int SMEM64  = (64 * 72 + 64 * 72) * 2;   // 18432 B
    cudaFuncSetAttribute(gemm_mma<128, true, true, false>,  cudaFuncAttributeMaxDynamicSharedMemorySize, SMEM128);
    cudaFuncSetAttribute(gemm_mma<128, true, false, false>, cudaFuncAttributeMaxDynamicSharedMemorySize, SMEM128);
    cudaFuncSetAttribute(gemm_mma<64, false, false, true>,  cudaFuncAttributeMaxDynamicSharedMemorySize, SMEM64);

    // One-time side stream + fork/join events (created on the first, non-capture, call).
    static cudaStream_t s_side = nullptr;
    static cudaEvent_t s_fork = nullptr, s_join = nullptr;
    if (s_side == nullptr) {
        cudaStreamCreateWithFlags(&s_side, cudaStreamNonBlocking);
        cudaEventCreateWithFlags(&s_fork, cudaEventDisableTiming);
        cudaEventCreateWithFlags(&s_join, cudaEventDisableTiming);
    }

    const int gemm_grid = (NN + 63) / 64;  // 782
    const int agg_grid  = (NN + 7) / 8;

    // ---- forked phase: CSR build (side stream) || convert + SLP GEMM (main) ----
    convert_weights_kernel<<<(18432 + 255) / 256, 256>>>(fc_W, W, W_last, w16);
    cudaEventRecord(s_fork, 0);
    cudaStreamWaitEvent(s_side, s_fork, 0);

    zero_deg_kernel<<<(NN + 255) / 256, 256, 0, s_side>>>();
    hist_kernel<<<(NE / 4 + 255) / 256, 256, 0, s_side>>>(dst);
    gemm_mma<128, true, true, false><<<gemm_grid, 256, SMEM128>>>(   // profiled slot
        inputs, nullptr, w16, fc_b, nullptr, h16, NN);
    scan_kernel<<<1, 1024, 0, s_side>>>();
    fill_kernel<<<(NE / 4 + 255) / 256, 256, 0, s_side>>>(src, dst);

    cudaEventRecord(s_join, s_side);
    cudaStreamWaitEvent(0, s_join, 0);

    // ---- serial phase: 3 hidden GIN layers (all-fp16 state) ----
    for (int i = 0; i < 3; ++i) {
        aggregate_kernel<<<agg_grid, 256>>>(h16, x16, eps, i);
        gemm_mma<128, true, false, false><<<gemm_grid, 256, SMEM128>>>(
            nullptr, x16, w16 + (size_t)(1 + i) * 16384,
            b + (size_t)i * 128, nullptr, h16, NN);
    }

    // last GIN layer (no relu), fp32 straight into d_out
    aggregate_kernel<<<agg_grid, 256>>>(h16, x16, eps, 3);
    gemm_mma<64, false, false, true><<<gemm_grid, 256, SMEM64>>>(
        nullptr, x16, w16 + (size_t)4 * 16384, b_last, out, nullptr, NN);

    (void)in_sizes; (void)n_in; (void)out_size;
}